// round 12
// baseline (speedup 1.0000x reference)
#include <cuda_runtime.h>
#include <math.h>

// ---------------- problem constants ----------------
#define TSTEPS 1000
#define NIN    4096
#define RN     4000
#define OUTW   (2*RN)

// ---------------- fused pipeline config ----------------
#define CHAINBLKS 125          // 125 tiles x 32 columns = 4000 (both chains)
#define CTHR      512
#define LAG       256          // chain2 trails chain1 by LAG ticks
#define TTOT      (TSTEPS + LAG)

#define G_CG      63           // GEMM2 col groups of 64 (63*64 = 4032 >= 4000)
#define G_RB      8            // GEMM2 row blocks of 128
#define GBLKS     (G_CG * G_RB)            // 504
#define MEGABLKS  (CHAINBLKS + GBLKS)      // 629

#define NNZ_CAP 1800000

// ---------------- device scratch ----------------
__device__ float          d_vals1[NNZ_CAP];
__device__ unsigned short d_rows1[NNZ_CAP];
__device__ float          d_vals2[NNZ_CAP];
__device__ unsigned short d_rows2[NNZ_CAP];
__device__ int            d_colptr1[RN+1];
__device__ int            d_colptr2[RN+1];
__device__ int            d_cntW1[8*RN];
__device__ int            d_cntW2[8*RN];
__device__ float          d_U1[TSTEPS*RN];    // x @ Win1  (prior launch -> RO)
__device__ float          d_U2[TSTEPS*RN];    // V1 @ Win2 (written in-kernel!)
__device__ float          d_v1[2][RN];        // hot ping-pong states
__device__ float          d_v2[2][RN];
__device__ unsigned       g_ctr;              // chain barrier counter
__device__ unsigned       g_prog1;            // v1 steps published
__device__ unsigned       d_done2[G_RB];      // GEMM2 rowblock completion

// ---------------- packed f32x2 helpers -----------------
__device__ __forceinline__ unsigned long long dupf2(float v) {
    unsigned long long r;
    asm("mov.b64 %0, {%1, %2};" : "=l"(r) : "f"(v), "f"(v));
    return r;
}
__device__ __forceinline__ void fmaf2(unsigned long long &d,
                                      unsigned long long a,
                                      unsigned long long b) {
    asm("fma.rn.f32x2 %0, %1, %2, %0;" : "+l"(d) : "l"(a), "l"(b));
}
__device__ __forceinline__ float2 unpk(unsigned long long v) {
    float2 r;
    asm("mov.b64 {%0, %1}, %2;" : "=f"(r.x), "=f"(r.y) : "l"(v));
    return r;
}

// ---------------- scoped sync primitives ----------------
__device__ __forceinline__ void redAddRel(unsigned* p) {
    asm volatile("red.release.gpu.global.add.u32 [%0], 1;"
                 :: "l"(p) : "memory");
}
__device__ __forceinline__ unsigned ldAcq(const unsigned* p) {
    unsigned v;
    asm volatile("ld.acquire.gpu.global.u32 %0, [%1];"
                 : "=r"(v) : "l"(p) : "memory");
    return v;
}
__device__ __forceinline__ void stRel(unsigned* p, unsigned v) {
    asm volatile("st.release.gpu.global.u32 [%0], %1;"
                 :: "l"(p), "r"(v) : "memory");
}

// ---------------- init (reset sync state every replay) ----------------
__global__ void initKernel() {
    int idx = threadIdx.x;
    if (idx == 0) { g_ctr = 0u; g_prog1 = 0u; }
    if (idx < G_RB) d_done2[idx] = 0u;
}

// ---------------- sparse build: per-warp-range counts ----------------
__global__ void countKernel(const float* __restrict__ W1,
                            const float* __restrict__ W2) {
    int b = blockIdx.x;
    const float* W; int* cntW; int j0;
    if (b < 125) { W = W1; cntW = d_cntW1; j0 = b * 32; }
    else         { W = W2; cntW = d_cntW2; j0 = (b - 125) * 32; }
    int w = threadIdx.x >> 5, lane = threadIdx.x & 31;
    int j = j0 + lane;
    int c = 0;
    int i0 = w * 500, i1 = i0 + 500;
    for (int i = i0; i < i1; i++) c += (W[(size_t)i * RN + j] != 0.f);
    cntW[w * RN + j] = c;
}

// ---------------- exclusive scan ----------------
__global__ void scanKernel() {
    __shared__ int sA[4096], sB[4096];
    const int* cntW = (blockIdx.x == 0) ? d_cntW1 : d_cntW2;
    int* colptr     = (blockIdx.x == 0) ? d_colptr1 : d_colptr2;
    int tid = threadIdx.x;
    for (int i = tid; i < 4096; i += blockDim.x) {
        int tot = 0;
        if (i < RN)
            for (int w = 0; w < 8; w++) tot += cntW[w * RN + i];
        sA[i] = tot;
    }
    __syncthreads();
    int* src = sA; int* dst = sB;
    for (int off = 1; off < 4096; off <<= 1) {
        for (int i = tid; i < 4096; i += blockDim.x)
            dst[i] = src[i] + (i >= off ? src[i - off] : 0);
        __syncthreads();
        int* t = src; src = dst; dst = t;
    }
    for (int i = tid; i < RN; i += blockDim.x) colptr[i + 1] = src[i];
    if (tid == 0) colptr[0] = 0;
}

// ---------------- fill CSC ----------------
__global__ void fillKernel(const float* __restrict__ W1,
                           const float* __restrict__ W2) {
    int b = blockIdx.x;
    const float* W; const int* cntW; const int* colptr;
    float* vals; unsigned short* rows; int j0;
    if (b < 125) { W = W1; cntW = d_cntW1; colptr = d_colptr1;
                   vals = d_vals1; rows = d_rows1; j0 = b * 32; }
    else         { W = W2; cntW = d_cntW2; colptr = d_colptr2;
                   vals = d_vals2; rows = d_rows2; j0 = (b - 125) * 32; }
    int w = threadIdx.x >> 5, lane = threadIdx.x & 31;
    int j = j0 + lane;
    int p = colptr[j];
    for (int w2 = 0; w2 < 8; w2++)
        if (w2 < w) p += cntW[w2 * RN + j];
    int i0 = w * 500, i1 = i0 + 500;
    for (int i = i0; i < i1; i++) {
        float v = W[(size_t)i * RN + j];
        if (v != 0.f) { vals[p] = v; rows[p] = (unsigned short)i; p++; }
    }
}

// ---------------- GEMM1 (separate launch): d_U1 = x @ Win1 ------------------
// Proven R10 sgemmK; C resolved device-side (device globals must never be
// host-side kernel args).
__global__ __launch_bounds__(256) void sgemmK(const float* __restrict__ A,
                                              const float* __restrict__ B,
                                              int M, int N, int K,
                                              int lda, int ldb, int ldc) {
    float* __restrict__ C = d_U1;
    __shared__ float As[8][128];
    __shared__ float Bs[8][128];
    int tid = threadIdx.x;
    int tx = tid % 16, ty = tid / 16;
    int row0 = blockIdx.y * 128, col0 = blockIdx.x * 128;

    unsigned long long acc2[4][8];
#pragma unroll
    for (int p = 0; p < 4; p++)
#pragma unroll
        for (int j = 0; j < 8; j++) acc2[p][j] = 0ull;

    const int aRow = tid >> 1;
    const int aCol = (tid & 1) * 4;
    const int bRow = tid >> 5;
    const int bCol = (tid & 31) * 4;

    float4 a4 = make_float4(0.f, 0.f, 0.f, 0.f);
    if (row0 + aRow < M)
        a4 = *(const float4*)(A + (size_t)(row0 + aRow) * lda + aCol);
    float4 b4 = make_float4(0.f, 0.f, 0.f, 0.f);
    if (col0 + bCol < N)
        b4 = *(const float4*)(B + (size_t)bRow * ldb + col0 + bCol);

    for (int k0 = 0; k0 < K; k0 += 8) {
        As[aCol + 0][aRow] = a4.x; As[aCol + 1][aRow] = a4.y;
        As[aCol + 2][aRow] = a4.z; As[aCol + 3][aRow] = a4.w;
        *(float4*)(&Bs[bRow][bCol]) = b4;
        __syncthreads();

        if (k0 + 8 < K) {
            if (row0 + aRow < M)
                a4 = *(const float4*)(A + (size_t)(row0 + aRow) * lda + k0 + 8 + aCol);
            if (col0 + bCol < N)
                b4 = *(const float4*)(B + (size_t)(k0 + 8 + bRow) * ldb + col0 + bCol);
        }

#pragma unroll
        for (int kk = 0; kk < 8; kk++) {
            float4 a0 = *(const float4*)(&As[kk][ty * 4]);
            float4 a1 = *(const float4*)(&As[kk][64 + ty * 4]);
            float4 bb0 = *(const float4*)(&Bs[kk][tx * 4]);
            float4 bb1 = *(const float4*)(&Bs[kk][64 + tx * 4]);
            unsigned long long ap[4];
            ap[0] = reinterpret_cast<const ulonglong2*>(&a0)->x;
            ap[1] = reinterpret_cast<const ulonglong2*>(&a0)->y;
            ap[2] = reinterpret_cast<const ulonglong2*>(&a1)->x;
            ap[3] = reinterpret_cast<const ulonglong2*>(&a1)->y;
            unsigned long long bd[8];
            bd[0] = dupf2(bb0.x); bd[1] = dupf2(bb0.y);
            bd[2] = dupf2(bb0.z); bd[3] = dupf2(bb0.w);
            bd[4] = dupf2(bb1.x); bd[5] = dupf2(bb1.y);
            bd[6] = dupf2(bb1.z); bd[7] = dupf2(bb1.w);
#pragma unroll
            for (int p = 0; p < 4; p++)
#pragma unroll
                for (int j = 0; j < 8; j++)
                    fmaf2(acc2[p][j], ap[p], bd[j]);
        }
        __syncthreads();
    }

#pragma unroll
    for (int p = 0; p < 4; p++) {
        float2 u[8];
#pragma unroll
        for (int j = 0; j < 8; j++) u[j] = unpk(acc2[p][j]);
#pragma unroll
        for (int h = 0; h < 2; h++) {
            int i = 2 * p + h;
            int r = row0 + ((i < 4) ? (ty * 4 + i) : (64 + ty * 4 + i - 4));
            if (r >= M) continue;
            float4 v0 = make_float4(h ? u[0].y : u[0].x, h ? u[1].y : u[1].x,
                                    h ? u[2].y : u[2].x, h ? u[3].y : u[3].x);
            float4 v1 = make_float4(h ? u[4].y : u[4].x, h ? u[5].y : u[5].x,
                                    h ? u[6].y : u[6].x, h ? u[7].y : u[7].x);
            int c0 = col0 + tx * 4;
            int c1 = col0 + 64 + tx * 4;
            if (c0 < N) *(float4*)(C + (size_t)r * ldc + c0) = v0;
            if (c1 < N) *(float4*)(C + (size_t)r * ldc + c1) = v1;
        }
    }
}

// ---------------- GEMM2 role: d_U2[128x64 tile] = V1 @ Win2 -----------------
// Waits for chain1 progress (g_prog1), reads V1 rows from `out` coherently.
__device__ void gemm2_role(int p,
                           const float* __restrict__ Win2,
                           const float* __restrict__ out) {
    __shared__ float As[8][128];
    __shared__ float Bs[8][64];

    const int rb   = p / G_CG;
    const int cg   = p % G_CG;
    const int row0 = rb * 128;
    const int col0 = cg * 64;
    const int tid  = threadIdx.x;
    const int M = TSTEPS, N = RN, K = RN, lda = OUTW, ldb = RN, ldc = RN;

    if (tid == 0) {
        unsigned need = (unsigned)((row0 + 128 < TSTEPS) ? row0 + 128 : TSTEPS);
        while (ldAcq(&g_prog1) < need) __nanosleep(1000);
    }
    __syncthreads();

    unsigned long long acc[2][4];
#pragma unroll
    for (int pr = 0; pr < 2; pr++)
#pragma unroll
        for (int j = 0; j < 4; j++) acc[pr][j] = 0ull;

    const int tx   = tid & 15;
    const int ty   = tid >> 4;
    const int aRow = tid >> 2;
    const int aK   = (tid & 3) * 2;
    const int bK   = tid >> 6;
    const int bCol = tid & 63;

    for (int k0 = 0; k0 < K; k0 += 8) {
        float2 av = make_float2(0.f, 0.f);
        if (row0 + aRow < M)
            av = __ldcg(reinterpret_cast<const float2*>(
                     out + (size_t)(row0 + aRow) * lda + k0 + aK));
        As[aK][aRow] = av.x; As[aK + 1][aRow] = av.y;
        Bs[bK][bCol] = Win2[(size_t)(k0 + bK) * ldb + col0 + bCol];
        __syncthreads();

#pragma unroll
        for (int kk = 0; kk < 8; kk++) {
            float4 a4 = *reinterpret_cast<const float4*>(&As[kk][ty * 4]);
            float4 b4 = *reinterpret_cast<const float4*>(&Bs[kk][tx * 4]);
            unsigned long long ap0 = reinterpret_cast<const ulonglong2*>(&a4)->x;
            unsigned long long ap1 = reinterpret_cast<const ulonglong2*>(&a4)->y;
            unsigned long long bd[4];
            bd[0] = dupf2(b4.x); bd[1] = dupf2(b4.y);
            bd[2] = dupf2(b4.z); bd[3] = dupf2(b4.w);
#pragma unroll
            for (int j = 0; j < 4; j++) {
                fmaf2(acc[0][j], ap0, bd[j]);
                fmaf2(acc[1][j], ap1, bd[j]);
            }
        }
        __syncthreads();
    }

#pragma unroll
    for (int pr = 0; pr < 2; pr++) {
        float2 u[4];
#pragma unroll
        for (int j = 0; j < 4; j++) u[j] = unpk(acc[pr][j]);
#pragma unroll
        for (int h = 0; h < 2; h++) {
            int r = row0 + ty * 4 + pr * 2 + h;
            if (r < M) {
#pragma unroll
                for (int j = 0; j < 4; j++) {
                    int cc = col0 + tx * 4 + j;
                    if (cc < N) d_U2[(size_t)r * ldc + cc] = h ? u[j].y : u[j].x;
                }
            }
        }
    }

    __syncthreads();
    if (tid == 0) redAddRel(&d_done2[rb]);
}

// ---------------- dual-chain tick role ---------------------------------------
// Block b owns columns [b*32, b*32+32) of BOTH reservoirs.
// Tick k: chain1 step t1=k (warps 0-7), chain2 step t2=k-LAG (warps 8-15).
// U1 is read-only in this kernel (__ldg OK); U2 is written concurrently by
// gemm2_role -> MUST use __ldcg (the R11 bug).
__device__ void chain_role(int b, float* __restrict__ out) {
    __shared__ float vs1[RN];
    __shared__ float vs2[RN];
    __shared__ int s_c1[33];
    __shared__ int s_c2[33];

    const int tid  = threadIdx.x;
    const int lane = tid & 31;
    const int wrp  = tid >> 5;          // 0..15
    const int j0   = b * 32;

    if (tid < 33)       s_c1[tid]      = __ldg(&d_colptr1[j0 + tid]);
    else if (tid < 66)  s_c2[tid - 33] = __ldg(&d_colptr2[j0 + tid - 33]);

    for (int k = 0; k < TTOT; k++) {
        const int t1 = k;
        const int t2 = k - LAG;

        // wait for GEMM2 rowblock at chain2 rowblock boundaries (tid0 only)
        if (tid == 0) {
            if (t2 >= 0 && t2 <= TSTEPS - 1 && (t2 & 127) == 0)
                while (ldAcq(&d_done2[t2 >> 7]) < (unsigned)G_CG) __nanosleep(200);
        }

        // stage previous states into smem (L1 bypass: written by other SMs)
        if (t1 >= 1 && t1 <= TSTEPS - 1) {
            const float4* s = reinterpret_cast<const float4*>(d_v1[(t1 - 1) & 1]);
            for (int i = tid; i < RN / 4; i += CTHR)
                reinterpret_cast<float4*>(vs1)[i] = __ldcg(s + i);
        }
        if (t2 >= 1 && t2 <= TSTEPS - 1) {
            const float4* s = reinterpret_cast<const float4*>(d_v2[(t2 - 1) & 1]);
            for (int i = tid; i < RN / 4; i += CTHR)
                reinterpret_cast<float4*>(vs2)[i] = __ldcg(s + i);
        }
        __syncthreads();   // orders s_c (first tick) + tid0's d_done2 acquire

        const int c   = lane >> 3;      // 0..3: column within warp's quad
        const int sub = lane & 7;       // 0..7: lanes per column

        if (wrp < 8) {
            if (t1 <= TSTEPS - 1) {
                const int lc  = wrp * 4 + c;
                const int col = j0 + lc;
                float acc = 0.f;
                if (t1 > 0) {
                    const int pe = s_c1[lc + 1];
                    for (int p = s_c1[lc] + sub; p < pe; p += 8)
                        acc += __ldg(&d_vals1[p]) * vs1[__ldg(&d_rows1[p])];
                    acc += __shfl_down_sync(0xffffffffu, acc, 4);
                    acc += __shfl_down_sync(0xffffffffu, acc, 2);
                    acc += __shfl_down_sync(0xffffffffu, acc, 1);
                }
                if (sub == 0) {
                    float u  = __ldg(&d_U1[(size_t)t1 * RN + col]);  // RO here
                    float vn = (t1 > 0)
                             ? 0.5f * vs1[col] + 0.5f * tanhf(acc + u)
                             : 0.5f * tanhf(u);
                    d_v1[t1 & 1][col] = vn;
                    out[(size_t)t1 * OUTW + col] = vn;
                }
            }
        } else {
            if (t2 >= 0 && t2 <= TSTEPS - 1) {
                const int lc  = (wrp - 8) * 4 + c;
                const int col = j0 + lc;
                float acc = 0.f;
                if (t2 > 0) {
                    const int pe = s_c2[lc + 1];
                    for (int p = s_c2[lc] + sub; p < pe; p += 8)
                        acc += __ldg(&d_vals2[p]) * vs2[__ldg(&d_rows2[p])];
                    acc += __shfl_down_sync(0xffffffffu, acc, 4);
                    acc += __shfl_down_sync(0xffffffffu, acc, 2);
                    acc += __shfl_down_sync(0xffffffffu, acc, 1);
                }
                if (sub == 0) {
                    // U2 is produced concurrently -> coherent load (R11 fix)
                    float u  = __ldcg(&d_U2[(size_t)t2 * RN + col]);
                    float vn = (t2 > 0)
                             ? 0.5f * vs2[col] + 0.5f * tanhf(acc + u)
                             : 0.5f * tanhf(u);
                    d_v2[t2 & 1][col] = vn;
                    out[(size_t)t2 * OUTW + RN + col] = vn;
                }
            }
        }

        // grid barrier over the 125 chain blocks (skip after final tick)
        if (k < TTOT - 1) {
            __syncthreads();
            if (tid == 0) {
                redAddRel(&g_ctr);
                unsigned target = (unsigned)(k + 1) * (unsigned)CHAINBLKS;
                while (ldAcq(&g_ctr) < target) { }
                if (b == 0 && k < TSTEPS)
                    stRel(&g_prog1, (unsigned)(k + 1));   // v1 steps published
            }
            __syncthreads();
        }
    }
}

// ---------------- fused kernel: chains + GEMM2 ----------------
__global__ __launch_bounds__(CTHR, 2)
void fusedKernel(const float* __restrict__ Win2, float* __restrict__ out) {
    const int bid = blockIdx.x;
    if (bid < CHAINBLKS) chain_role(bid, out);
    else                 gemm2_role(bid - CHAINBLKS, Win2, out);
}

// ---------------- launch ----------------
extern "C" void kernel_launch(void* const* d_in, const int* in_sizes, int n_in,
                              void* d_out, int out_size) {
    const float* x    = (const float*)d_in[0];
    const float* Win1 = (const float*)d_in[1];
    const float* W1   = (const float*)d_in[2];
    const float* Win2 = (const float*)d_in[3];
    const float* W2   = (const float*)d_in[4];
    float* out = (float*)d_out;
    (void)in_sizes; (void)n_in; (void)out_size;

    initKernel<<<1, 32>>>();
    countKernel<<<250, 256>>>(W1, W2);
    scanKernel<<<2, 1024>>>();
    fillKernel<<<250, 256>>>(W1, W2);

    // U1 = x[1000,4096] @ Win1[4096,4000]  (prior launch -> U1 is RO in fused)
    dim3 gg((RN + 127) / 128, (TSTEPS + 127) / 128);
    sgemmK<<<gg, 256>>>(x, Win1, TSTEPS, RN, NIN, NIN, RN, RN);

    // fused: dual-chain ticks + GEMM2 (U2 = V1 @ Win2) hidden behind them
    fusedKernel<<<MEGABLKS, CTHR>>>(Win2, out);
}

// round 13
// speedup vs baseline: 1.0219x; 1.0219x over previous
#include <cuda_runtime.h>
#include <math.h>

// ---------------- problem constants ----------------
#define TSTEPS 1000
#define NIN    4096
#define RN     4000
#define OUTW   (2*RN)
#define ALPHA  0.5f

// ---------------- persistent loop config ----------------
#define NBLK   63              // 63 tiles x 64 columns (last block partial)
#define COLSB  64
#define NTHR   1024

#define NNZ_CAP 1800000

// ---------------- device scratch ----------------
__device__ float          d_vals1[NNZ_CAP];
__device__ unsigned short d_rows1[NNZ_CAP];
__device__ float          d_vals2[NNZ_CAP];
__device__ unsigned short d_rows2[NNZ_CAP];
__device__ int            d_colptr1[RN+1];
__device__ int            d_colptr2[RN+1];
__device__ int            d_cntW1[8*RN];
__device__ int            d_cntW2[8*RN];
__device__ float          d_U1[TSTEPS*RN];    // x @ Win1   (16 MB)
__device__ float          d_U2[TSTEPS*RN];    // V1 @ Win2  (16 MB)
__device__ float          d_v[2][RN];         // hot ping-pong state
__device__ unsigned       g_ctr1;             // monotonic barrier counters
__device__ unsigned       g_ctr2;

// ---------------- packed f32x2 helpers (sm_103a FFMA2 pipe) -----------------
__device__ __forceinline__ unsigned long long dupf2(float v) {
    unsigned long long r;
    asm("mov.b64 %0, {%1, %2};" : "=l"(r) : "f"(v), "f"(v));
    return r;
}
__device__ __forceinline__ void fmaf2(unsigned long long &d,
                                      unsigned long long a,
                                      unsigned long long b) {
    asm("fma.rn.f32x2 %0, %1, %2, %0;" : "+l"(d) : "l"(a), "l"(b));
}
__device__ __forceinline__ float2 unpk(unsigned long long v) {
    float2 r;
    asm("mov.b64 {%0, %1}, %2;" : "=f"(r.x), "=f"(r.y) : "l"(v));
    return r;
}

// ---------------- scoped sync primitives ----------------
__device__ __forceinline__ void redAddRel(unsigned* p) {
    asm volatile("red.release.gpu.global.add.u32 [%0], 1;"
                 :: "l"(p) : "memory");
}
__device__ __forceinline__ unsigned ldAcq(const unsigned* p) {
    unsigned v;
    asm volatile("ld.acquire.gpu.global.u32 %0, [%1];"
                 : "=r"(v) : "l"(p) : "memory");
    return v;
}

// ---------------- init (reset counters every replay — graph determinism) ----
__global__ void initKernel() {
    if (threadIdx.x == 0) { g_ctr1 = 0u; g_ctr2 = 0u; }
}

// ---------------- sparse build: per-warp-range counts ----------------
__global__ void countKernel(const float* __restrict__ W1,
                            const float* __restrict__ W2) {
    int b = blockIdx.x;
    const float* W; int* cntW; int j0;
    if (b < 125) { W = W1; cntW = d_cntW1; j0 = b * 32; }
    else         { W = W2; cntW = d_cntW2; j0 = (b - 125) * 32; }
    int w = threadIdx.x >> 5, lane = threadIdx.x & 31;
    int j = j0 + lane;
    int c = 0;
    int i0 = w * 500, i1 = i0 + 500;
    for (int i = i0; i < i1; i++) c += (W[(size_t)i * RN + j] != 0.f);
    cntW[w * RN + j] = c;
}

// ---------------- exclusive scan ----------------
__global__ void scanKernel() {
    __shared__ int sA[4096], sB[4096];
    const int* cntW = (blockIdx.x == 0) ? d_cntW1 : d_cntW2;
    int* colptr     = (blockIdx.x == 0) ? d_colptr1 : d_colptr2;
    int tid = threadIdx.x;
    for (int i = tid; i < 4096; i += blockDim.x) {
        int tot = 0;
        if (i < RN)
            for (int w = 0; w < 8; w++) tot += cntW[w * RN + i];
        sA[i] = tot;
    }
    __syncthreads();
    int* src = sA; int* dst = sB;
    for (int off = 1; off < 4096; off <<= 1) {
        for (int i = tid; i < 4096; i += blockDim.x)
            dst[i] = src[i] + (i >= off ? src[i - off] : 0);
        __syncthreads();
        int* t = src; src = dst; dst = t;
    }
    for (int i = tid; i < RN; i += blockDim.x) colptr[i + 1] = src[i];
    if (tid == 0) colptr[0] = 0;
}

// ---------------- fill CSC ----------------
__global__ void fillKernel(const float* __restrict__ W1,
                           const float* __restrict__ W2) {
    int b = blockIdx.x;
    const float* W; const int* cntW; const int* colptr;
    float* vals; unsigned short* rows; int j0;
    if (b < 125) { W = W1; cntW = d_cntW1; colptr = d_colptr1;
                   vals = d_vals1; rows = d_rows1; j0 = b * 32; }
    else         { W = W2; cntW = d_cntW2; colptr = d_colptr2;
                   vals = d_vals2; rows = d_rows2; j0 = (b - 125) * 32; }
    int w = threadIdx.x >> 5, lane = threadIdx.x & 31;
    int j = j0 + lane;
    int p = colptr[j];
    for (int w2 = 0; w2 < 8; w2++)
        if (w2 < w) p += cntW[w2 * RN + j];
    int i0 = w * 500, i1 = i0 + 500;
    for (int i = i0; i < i1; i++) {
        float v = W[(size_t)i * RN + j];
        if (v != 0.f) { vals[p] = v; rows[p] = (unsigned short)i; p++; }
    }
}

// ---------------- SGEMM (f32x2 packed, reg double-buffer) -------------------
// C = which ? d_U2 : d_U1 (resolved in device code; device globals must never
// be passed as host-side kernel args — that was the R3/R4 bug).
__global__ __launch_bounds__(256) void sgemmK(const float* __restrict__ A,
                                              const float* __restrict__ B,
                                              int which,
                                              int M, int N, int K,
                                              int lda, int ldb, int ldc) {
    float* __restrict__ C = which ? d_U2 : d_U1;
    __shared__ float As[8][128];
    __shared__ float Bs[8][128];
    int tid = threadIdx.x;
    int tx = tid % 16, ty = tid / 16;
    int row0 = blockIdx.y * 128, col0 = blockIdx.x * 128;

    unsigned long long acc2[4][8];   // [row-pair][col]
#pragma unroll
    for (int p = 0; p < 4; p++)
#pragma unroll
        for (int j = 0; j < 8; j++) acc2[p][j] = 0ull;

    const int aRow = tid >> 1;
    const int aCol = (tid & 1) * 4;
    const int bRow = tid >> 5;
    const int bCol = (tid & 31) * 4;

    float4 a4 = make_float4(0.f, 0.f, 0.f, 0.f);
    if (row0 + aRow < M)
        a4 = *(const float4*)(A + (size_t)(row0 + aRow) * lda + aCol);
    float4 b4 = make_float4(0.f, 0.f, 0.f, 0.f);
    if (col0 + bCol < N)
        b4 = *(const float4*)(B + (size_t)bRow * ldb + col0 + bCol);

    for (int k0 = 0; k0 < K; k0 += 8) {
        As[aCol + 0][aRow] = a4.x; As[aCol + 1][aRow] = a4.y;
        As[aCol + 2][aRow] = a4.z; As[aCol + 3][aRow] = a4.w;
        *(float4*)(&Bs[bRow][bCol]) = b4;
        __syncthreads();

        if (k0 + 8 < K) {
            if (row0 + aRow < M)
                a4 = *(const float4*)(A + (size_t)(row0 + aRow) * lda + k0 + 8 + aCol);
            if (col0 + bCol < N)
                b4 = *(const float4*)(B + (size_t)(k0 + 8 + bRow) * ldb + col0 + bCol);
        }

#pragma unroll
        for (int kk = 0; kk < 8; kk++) {
            float4 a0 = *(const float4*)(&As[kk][ty * 4]);
            float4 a1 = *(const float4*)(&As[kk][64 + ty * 4]);
            float4 bb0 = *(const float4*)(&Bs[kk][tx * 4]);
            float4 bb1 = *(const float4*)(&Bs[kk][64 + tx * 4]);
            unsigned long long ap[4];
            ap[0] = reinterpret_cast<const ulonglong2*>(&a0)->x;
            ap[1] = reinterpret_cast<const ulonglong2*>(&a0)->y;
            ap[2] = reinterpret_cast<const ulonglong2*>(&a1)->x;
            ap[3] = reinterpret_cast<const ulonglong2*>(&a1)->y;
            unsigned long long bd[8];
            bd[0] = dupf2(bb0.x); bd[1] = dupf2(bb0.y);
            bd[2] = dupf2(bb0.z); bd[3] = dupf2(bb0.w);
            bd[4] = dupf2(bb1.x); bd[5] = dupf2(bb1.y);
            bd[6] = dupf2(bb1.z); bd[7] = dupf2(bb1.w);
#pragma unroll
            for (int p = 0; p < 4; p++)
#pragma unroll
                for (int j = 0; j < 8; j++)
                    fmaf2(acc2[p][j], ap[p], bd[j]);
        }
        __syncthreads();
    }

#pragma unroll
    for (int p = 0; p < 4; p++) {
        float2 u[8];
#pragma unroll
        for (int j = 0; j < 8; j++) u[j] = unpk(acc2[p][j]);
#pragma unroll
        for (int h = 0; h < 2; h++) {
            int i = 2 * p + h;
            int r = row0 + ((i < 4) ? (ty * 4 + i) : (64 + ty * 4 + i - 4));
            if (r >= M) continue;
            float4 v0 = make_float4(h ? u[0].y : u[0].x, h ? u[1].y : u[1].x,
                                    h ? u[2].y : u[2].x, h ? u[3].y : u[3].x);
            float4 v1 = make_float4(h ? u[4].y : u[4].x, h ? u[5].y : u[5].x,
                                    h ? u[6].y : u[6].x, h ? u[7].y : u[7].x);
            int c0 = col0 + tx * 4;
            int c1 = col0 + 64 + tx * 4;
            if (c0 < N) *(float4*)(C + (size_t)r * ldc + c0) = v0;
            if (c1 < N) *(float4*)(C + (size_t)r * ldc + c1) = v1;
        }
    }
}

// ---------------- grid barrier: RED arrival + counter poll (R10-proven) -----
__device__ __forceinline__ void gsyncC(unsigned target, unsigned* ctr) {
    __syncthreads();
    if (threadIdx.x == 0) {
        redAddRel(ctr);                  // fire-and-forget arrival
        while (ldAcq(ctr) < target) { }  // counter reaching target = release
    }
    __syncthreads();
}

// ---------------- sparse-only recurrence (shared by both chains) ------------
// Block b owns columns [b*64, b*64+64) (last block partial). CSC slice
// (~154 KB) is L1-resident after step 1. State ping-pongs through d_v[2];
// out rows are archive-only (consumed by the NEXT kernel launch).
// v(t) = 0.5*v(t-1) + 0.5*tanh( v(t-1)@W + U[t] ),  v(-1)=0
// Depth-2 safety: writes to d_v[(t+1)&1] happen only after barrier t+1, which
// requires all blocks to have finished reading d_v[(t-1)&1] (same parity).
__device__ __forceinline__ void esn_chain(const int* __restrict__ colptr,
                                          const float* __restrict__ gvals,
                                          const unsigned short* __restrict__ grows,
                                          const float* __restrict__ U,
                                          float* __restrict__ out, int ofs,
                                          unsigned* ctr) {
    __shared__ float vs[RN];
    __shared__ int s_cst[COLSB + 1];

    const int tid  = threadIdx.x;
    const int lane = tid & 31;
    const int wrp  = tid >> 5;              // 0..31
    const int half = lane >> 4;             // 0/1: which column of the pair
    const int sub  = lane & 15;             // 16 lanes per column
    const int j0   = blockIdx.x * COLSB;
    const int lc   = wrp * 2 + half;        // 0..63 local column
    const int col  = j0 + lc;

    if (tid < COLSB + 1) {
        int idx = j0 + tid;
        if (idx > RN) idx = RN;             // clamp: empty tail columns
        s_cst[tid] = __ldg(&colptr[idx]);
    }

    // t = 0 : v(0) = 0.5*tanh(U[0])
    if (tid < COLSB) {
        int j = j0 + tid;
        if (j < RN) {
            float vn = ALPHA * tanhf(__ldg(&U[j]));
            d_v[0][j] = vn;
            out[(size_t)0 * OUTW + ofs + j] = vn;
        }
    }
    gsyncC(1u * NBLK, ctr);                 // also orders s_cst for the loop

    for (int t = 1; t < TSTEPS; t++) {
        const float* __restrict__ vsrc = d_v[(t - 1) & 1];
        float*       __restrict__ vdst = d_v[t & 1];

        // prefetch U[t] (independent of staging)
        float uval = 0.f;
        if (sub == 0 && col < RN)
            uval = __ldg(&U[(size_t)t * RN + col]);

        // stage v(t-1) into smem (bypass L1: written by other SMs)
        const float4* vp = reinterpret_cast<const float4*>(vsrc);
        for (int i = tid; i < RN / 4; i += NTHR)
            reinterpret_cast<float4*>(vs)[i] = __ldcg(vp + i);
        __syncthreads();

        // 16 lanes -> one column; publish immediately when done
        {
            const int ps = s_cst[lc];
            const int pe = s_cst[lc + 1];
            float acc = 0.f;
            for (int p = ps + sub; p < pe; p += 16)
                acc += __ldg(&gvals[p]) * vs[__ldg(&grows[p])];
            acc += __shfl_down_sync(0xffffffffu, acc, 8);
            acc += __shfl_down_sync(0xffffffffu, acc, 4);
            acc += __shfl_down_sync(0xffffffffu, acc, 2);
            acc += __shfl_down_sync(0xffffffffu, acc, 1);
            if (sub == 0 && col < RN) {
                float z  = acc + uval;
                float vn = (1.f - ALPHA) * vs[col] + ALPHA * tanhf(z);
                vdst[col] = vn;                            // hot publish
                out[(size_t)t * OUTW + ofs + col] = vn;    // archive
            }
        }

        if (t < TSTEPS - 1)
            gsyncC((unsigned)(t + 1) * NBLK, ctr);
    }
}

__global__ __launch_bounds__(NTHR, 1) void esn1Kernel(float* __restrict__ out) {
    esn_chain(d_colptr1, d_vals1, d_rows1, d_U1, out, 0, &g_ctr1);
}

__global__ __launch_bounds__(NTHR, 1) void esn2Kernel(float* __restrict__ out) {
    esn_chain(d_colptr2, d_vals2, d_rows2, d_U2, out, RN, &g_ctr2);
}

// ---------------- launch ----------------
extern "C" void kernel_launch(void* const* d_in, const int* in_sizes, int n_in,
                              void* d_out, int out_size) {
    const float* x    = (const float*)d_in[0];
    const float* Win1 = (const float*)d_in[1];
    const float* W1   = (const float*)d_in[2];
    const float* Win2 = (const float*)d_in[3];
    const float* W2   = (const float*)d_in[4];
    float* out = (float*)d_out;
    (void)in_sizes; (void)n_in; (void)out_size;

    initKernel<<<1, 32>>>();
    countKernel<<<250, 256>>>(W1, W2);
    scanKernel<<<2, 1024>>>();
    fillKernel<<<250, 256>>>(W1, W2);

    dim3 gg((RN + 127) / 128, (TSTEPS + 127) / 128);
    // U1 = x[1000,4096] @ Win1[4096,4000]
    sgemmK<<<gg, 256>>>(x, Win1, 0, TSTEPS, RN, NIN, NIN, RN, RN);

    // v1 chain -> out[:, 0:4000]
    esn1Kernel<<<NBLK, NTHR>>>(out);

    // U2 = V1[1000,4000] @ Win2[4000,4000]  (V1 rows in out, stride OUTW)
    sgemmK<<<gg, 256>>>(out, Win2, 1, TSTEPS, RN, RN, OUTW, RN, RN);

    // v2 chain -> out[:, 4000:8000]
    esn2Kernel<<<NBLK, NTHR>>>(out);
}

// round 14
// speedup vs baseline: 1.4981x; 1.4660x over previous
#include <cuda_runtime.h>
#include <math.h>

// ---------------- problem constants ----------------
#define TSTEPS 1000
#define NIN    4096
#define RN     4000
#define OUTW   (2*RN)
#define ALPHA  0.5f

// ---------------- persistent loop config (R10-proven) ----------------
#define NBLK   125             // 125 tiles x 32 columns = 4000
#define NTHR   1024

#define NNZ_CAP 1800000

// ---------------- device scratch ----------------
__device__ float          d_vals1[NNZ_CAP];
__device__ unsigned short d_rows1[NNZ_CAP];
__device__ float          d_vals2[NNZ_CAP];
__device__ unsigned short d_rows2[NNZ_CAP];
__device__ int            d_colptr1[RN+1];
__device__ int            d_colptr2[RN+1];
__device__ int            d_cntW1[8*RN];
__device__ int            d_cntW2[8*RN];
__device__ float          d_U1[TSTEPS*RN];    // x @ Win1   (16 MB)
__device__ float          d_U2[TSTEPS*RN];    // V1 @ Win2  (16 MB)
__device__ float          d_v[2][RN];         // hot ping-pong state
__device__ unsigned       g_ctr1;             // monotonic barrier counters
__device__ unsigned       g_ctr2;

// ---------------- packed f32x2 helpers (sm_103a FFMA2 pipe) -----------------
__device__ __forceinline__ unsigned long long dupf2(float v) {
    unsigned long long r;
    asm("mov.b64 %0, {%1, %2};" : "=l"(r) : "f"(v), "f"(v));
    return r;
}
__device__ __forceinline__ void fmaf2(unsigned long long &d,
                                      unsigned long long a,
                                      unsigned long long b) {
    asm("fma.rn.f32x2 %0, %1, %2, %0;" : "+l"(d) : "l"(a), "l"(b));
}
__device__ __forceinline__ float2 unpk(unsigned long long v) {
    float2 r;
    asm("mov.b64 {%0, %1}, %2;" : "=f"(r.x), "=f"(r.y) : "l"(v));
    return r;
}

// ---------------- scoped sync primitives ----------------
__device__ __forceinline__ void redAddRel(unsigned* p) {
    asm volatile("red.release.gpu.global.add.u32 [%0], 1;"
                 :: "l"(p) : "memory");
}
__device__ __forceinline__ unsigned ldAcq(const unsigned* p) {
    unsigned v;
    asm volatile("ld.acquire.gpu.global.u32 %0, [%1];"
                 : "=r"(v) : "l"(p) : "memory");
    return v;
}

// ---------------- GEMM1 tile body: d_U1[128x128 tile] = x @ Win1 ------------
// (device function so it can be a role inside the fused build kernel)
__device__ void gemm1_tile(const float* __restrict__ A,
                           const float* __restrict__ B,
                           int row0, int col0) {
    const int M = TSTEPS, N = RN, K = NIN, lda = NIN, ldb = RN, ldc = RN;
    float* __restrict__ C = d_U1;
    __shared__ float As[8][128];
    __shared__ float Bs[8][128];
    int tid = threadIdx.x;
    int tx = tid % 16, ty = tid / 16;

    unsigned long long acc2[4][8];   // [row-pair][col]
#pragma unroll
    for (int p = 0; p < 4; p++)
#pragma unroll
        for (int j = 0; j < 8; j++) acc2[p][j] = 0ull;

    const int aRow = tid >> 1;
    const int aCol = (tid & 1) * 4;
    const int bRow = tid >> 5;
    const int bCol = (tid & 31) * 4;

    float4 a4 = make_float4(0.f, 0.f, 0.f, 0.f);
    if (row0 + aRow < M)
        a4 = *(const float4*)(A + (size_t)(row0 + aRow) * lda + aCol);
    float4 b4 = make_float4(0.f, 0.f, 0.f, 0.f);
    if (col0 + bCol < N)
        b4 = *(const float4*)(B + (size_t)bRow * ldb + col0 + bCol);

    for (int k0 = 0; k0 < K; k0 += 8) {
        As[aCol + 0][aRow] = a4.x; As[aCol + 1][aRow] = a4.y;
        As[aCol + 2][aRow] = a4.z; As[aCol + 3][aRow] = a4.w;
        *(float4*)(&Bs[bRow][bCol]) = b4;
        __syncthreads();

        if (k0 + 8 < K) {
            if (row0 + aRow < M)
                a4 = *(const float4*)(A + (size_t)(row0 + aRow) * lda + k0 + 8 + aCol);
            if (col0 + bCol < N)
                b4 = *(const float4*)(B + (size_t)(k0 + 8 + bRow) * ldb + col0 + bCol);
        }

#pragma unroll
        for (int kk = 0; kk < 8; kk++) {
            float4 a0 = *(const float4*)(&As[kk][ty * 4]);
            float4 a1 = *(const float4*)(&As[kk][64 + ty * 4]);
            float4 bb0 = *(const float4*)(&Bs[kk][tx * 4]);
            float4 bb1 = *(const float4*)(&Bs[kk][64 + tx * 4]);
            unsigned long long ap[4];
            ap[0] = reinterpret_cast<const ulonglong2*>(&a0)->x;
            ap[1] = reinterpret_cast<const ulonglong2*>(&a0)->y;
            ap[2] = reinterpret_cast<const ulonglong2*>(&a1)->x;
            ap[3] = reinterpret_cast<const ulonglong2*>(&a1)->y;
            unsigned long long bd[8];
            bd[0] = dupf2(bb0.x); bd[1] = dupf2(bb0.y);
            bd[2] = dupf2(bb0.z); bd[3] = dupf2(bb0.w);
            bd[4] = dupf2(bb1.x); bd[5] = dupf2(bb1.y);
            bd[6] = dupf2(bb1.z); bd[7] = dupf2(bb1.w);
#pragma unroll
            for (int p = 0; p < 4; p++)
#pragma unroll
                for (int j = 0; j < 8; j++)
                    fmaf2(acc2[p][j], ap[p], bd[j]);
        }
        __syncthreads();
    }

#pragma unroll
    for (int p = 0; p < 4; p++) {
        float2 u[8];
#pragma unroll
        for (int j = 0; j < 8; j++) u[j] = unpk(acc2[p][j]);
#pragma unroll
        for (int h = 0; h < 2; h++) {
            int i = 2 * p + h;
            int r = row0 + ((i < 4) ? (ty * 4 + i) : (64 + ty * 4 + i - 4));
            if (r >= M) continue;
            float4 v0 = make_float4(h ? u[0].y : u[0].x, h ? u[1].y : u[1].x,
                                    h ? u[2].y : u[2].x, h ? u[3].y : u[3].x);
            float4 v1 = make_float4(h ? u[4].y : u[4].x, h ? u[5].y : u[5].x,
                                    h ? u[6].y : u[6].x, h ? u[7].y : u[7].x);
            int c0 = col0 + tx * 4;
            int c1 = col0 + 64 + tx * 4;
            if (c0 < N) *(float4*)(C + (size_t)r * ldc + c0) = v0;
            if (c1 < N) *(float4*)(C + (size_t)r * ldc + c1) = v1;
        }
    }
}

// ---------------- fused build kernel: count roles + GEMM1 roles -------------
// Blocks 0..249: nnz counting (reads W1/W2, writes d_cntW*).
// Blocks 250..505: GEMM1 tiles (reads x/Win1, writes d_U1).
// Roles share NO data -> no synchronization, no barrier-pacing hazard.
// Block 0 thread 0 also resets the esn barrier counters (replay determinism).
__global__ __launch_bounds__(256) void buildGemm1Kernel(
        const float* __restrict__ W1, const float* __restrict__ W2,
        const float* __restrict__ x,  const float* __restrict__ Win1) {
    int b = blockIdx.x;
    if (b < 250) {
        if (b == 0 && threadIdx.x == 0) { g_ctr1 = 0u; g_ctr2 = 0u; }
        const float* W; int* cntW; int j0;
        if (b < 125) { W = W1; cntW = d_cntW1; j0 = b * 32; }
        else         { W = W2; cntW = d_cntW2; j0 = (b - 125) * 32; }
        int w = threadIdx.x >> 5, lane = threadIdx.x & 31;
        int j = j0 + lane;
        int c = 0;
        int i0 = w * 500, i1 = i0 + 500;
        for (int i = i0; i < i1; i++) c += (W[(size_t)i * RN + j] != 0.f);
        cntW[w * RN + j] = c;
    } else {
        int p = b - 250;                   // 0..255
        gemm1_tile(x, Win1, (p >> 5) * 128, (p & 31) * 128);
    }
}

// ---------------- exclusive scan ----------------
__global__ void scanKernel() {
    __shared__ int sA[4096], sB[4096];
    const int* cntW = (blockIdx.x == 0) ? d_cntW1 : d_cntW2;
    int* colptr     = (blockIdx.x == 0) ? d_colptr1 : d_colptr2;
    int tid = threadIdx.x;
    for (int i = tid; i < 4096; i += blockDim.x) {
        int tot = 0;
        if (i < RN)
            for (int w = 0; w < 8; w++) tot += cntW[w * RN + i];
        sA[i] = tot;
    }
    __syncthreads();
    int* src = sA; int* dst = sB;
    for (int off = 1; off < 4096; off <<= 1) {
        for (int i = tid; i < 4096; i += blockDim.x)
            dst[i] = src[i] + (i >= off ? src[i - off] : 0);
        __syncthreads();
        int* t = src; src = dst; dst = t;
    }
    for (int i = tid; i < RN; i += blockDim.x) colptr[i + 1] = src[i];
    if (tid == 0) colptr[0] = 0;
}

// ---------------- fill CSC ----------------
__global__ void fillKernel(const float* __restrict__ W1,
                           const float* __restrict__ W2) {
    int b = blockIdx.x;
    const float* W; const int* cntW; const int* colptr;
    float* vals; unsigned short* rows; int j0;
    if (b < 125) { W = W1; cntW = d_cntW1; colptr = d_colptr1;
                   vals = d_vals1; rows = d_rows1; j0 = b * 32; }
    else         { W = W2; cntW = d_cntW2; colptr = d_colptr2;
                   vals = d_vals2; rows = d_rows2; j0 = (b - 125) * 32; }
    int w = threadIdx.x >> 5, lane = threadIdx.x & 31;
    int j = j0 + lane;
    int p = colptr[j];
    for (int w2 = 0; w2 < 8; w2++)
        if (w2 < w) p += cntW[w2 * RN + j];
    int i0 = w * 500, i1 = i0 + 500;
    for (int i = i0; i < i1; i++) {
        float v = W[(size_t)i * RN + j];
        if (v != 0.f) { vals[p] = v; rows[p] = (unsigned short)i; p++; }
    }
}

// ---------------- SGEMM2 (separate launch): d_U2 = V1 @ Win2 ----------------
// C resolved device-side (device globals must never be host-side kernel args).
__global__ __launch_bounds__(256) void sgemm2K(const float* __restrict__ A,
                                               const float* __restrict__ B,
                                               int M, int N, int K,
                                               int lda, int ldb, int ldc) {
    float* __restrict__ C = d_U2;
    __shared__ float As[8][128];
    __shared__ float Bs[8][128];
    int tid = threadIdx.x;
    int tx = tid % 16, ty = tid / 16;
    int row0 = blockIdx.y * 128, col0 = blockIdx.x * 128;

    unsigned long long acc2[4][8];
#pragma unroll
    for (int p = 0; p < 4; p++)
#pragma unroll
        for (int j = 0; j < 8; j++) acc2[p][j] = 0ull;

    const int aRow = tid >> 1;
    const int aCol = (tid & 1) * 4;
    const int bRow = tid >> 5;
    const int bCol = (tid & 31) * 4;

    float4 a4 = make_float4(0.f, 0.f, 0.f, 0.f);
    if (row0 + aRow < M)
        a4 = *(const float4*)(A + (size_t)(row0 + aRow) * lda + aCol);
    float4 b4 = make_float4(0.f, 0.f, 0.f, 0.f);
    if (col0 + bCol < N)
        b4 = *(const float4*)(B + (size_t)bRow * ldb + col0 + bCol);

    for (int k0 = 0; k0 < K; k0 += 8) {
        As[aCol + 0][aRow] = a4.x; As[aCol + 1][aRow] = a4.y;
        As[aCol + 2][aRow] = a4.z; As[aCol + 3][aRow] = a4.w;
        *(float4*)(&Bs[bRow][bCol]) = b4;
        __syncthreads();

        if (k0 + 8 < K) {
            if (row0 + aRow < M)
                a4 = *(const float4*)(A + (size_t)(row0 + aRow) * lda + k0 + 8 + aCol);
            if (col0 + bCol < N)
                b4 = *(const float4*)(B + (size_t)(k0 + 8 + bRow) * ldb + col0 + bCol);
        }

#pragma unroll
        for (int kk = 0; kk < 8; kk++) {
            float4 a0 = *(const float4*)(&As[kk][ty * 4]);
            float4 a1 = *(const float4*)(&As[kk][64 + ty * 4]);
            float4 bb0 = *(const float4*)(&Bs[kk][tx * 4]);
            float4 bb1 = *(const float4*)(&Bs[kk][64 + tx * 4]);
            unsigned long long ap[4];
            ap[0] = reinterpret_cast<const ulonglong2*>(&a0)->x;
            ap[1] = reinterpret_cast<const ulonglong2*>(&a0)->y;
            ap[2] = reinterpret_cast<const ulonglong2*>(&a1)->x;
            ap[3] = reinterpret_cast<const ulonglong2*>(&a1)->y;
            unsigned long long bd[8];
            bd[0] = dupf2(bb0.x); bd[1] = dupf2(bb0.y);
            bd[2] = dupf2(bb0.z); bd[3] = dupf2(bb0.w);
            bd[4] = dupf2(bb1.x); bd[5] = dupf2(bb1.y);
            bd[6] = dupf2(bb1.z); bd[7] = dupf2(bb1.w);
#pragma unroll
            for (int p = 0; p < 4; p++)
#pragma unroll
                for (int j = 0; j < 8; j++)
                    fmaf2(acc2[p][j], ap[p], bd[j]);
        }
        __syncthreads();
    }

#pragma unroll
    for (int p = 0; p < 4; p++) {
        float2 u[8];
#pragma unroll
        for (int j = 0; j < 8; j++) u[j] = unpk(acc2[p][j]);
#pragma unroll
        for (int h = 0; h < 2; h++) {
            int i = 2 * p + h;
            int r = row0 + ((i < 4) ? (ty * 4 + i) : (64 + ty * 4 + i - 4));
            if (r >= M) continue;
            float4 v0 = make_float4(h ? u[0].y : u[0].x, h ? u[1].y : u[1].x,
                                    h ? u[2].y : u[2].x, h ? u[3].y : u[3].x);
            float4 v1 = make_float4(h ? u[4].y : u[4].x, h ? u[5].y : u[5].x,
                                    h ? u[6].y : u[6].x, h ? u[7].y : u[7].x);
            int c0 = col0 + tx * 4;
            int c1 = col0 + 64 + tx * 4;
            if (c0 < N) *(float4*)(C + (size_t)r * ldc + c0) = v0;
            if (c1 < N) *(float4*)(C + (size_t)r * ldc + c1) = v1;
        }
    }
}

// ---------------- grid barrier: RED arrival + counter poll (R10-proven) -----
__device__ __forceinline__ void gsyncC(unsigned target, unsigned* ctr) {
    __syncthreads();
    if (threadIdx.x == 0) {
        redAddRel(ctr);                  // fire-and-forget arrival
        while (ldAcq(ctr) < target) { }  // counter reaching target = release
    }
    __syncthreads();
}

// ---------------- sparse-only recurrence (R10-proven, + unroll) -------------
// Block b owns columns [b*32, b*32+32). CSC slice is L1-resident after step 1.
// v(t) = 0.5*v(t-1) + 0.5*tanh( v(t-1)@W + U[t] ),  v(-1)=0
__device__ __forceinline__ void esn_chain(const int* __restrict__ colptr,
                                          const float* __restrict__ gvals,
                                          const unsigned short* __restrict__ grows,
                                          const float* __restrict__ U,
                                          float* __restrict__ out, int ofs,
                                          unsigned* ctr) {
    __shared__ float vs[RN];
    __shared__ int s_cst[33];

    const int tid  = threadIdx.x;
    const int lane = tid & 31;
    const int wrp  = tid >> 5;          // 0..31 -> one column each
    const int j0   = blockIdx.x * 32;

    if (tid < 33) s_cst[tid] = __ldg(&colptr[j0 + tid]);

    // t = 0 : v(0) = 0.5*tanh(U[0])
    if (tid < 32) {
        int j = j0 + tid;
        float vn = ALPHA * tanhf(__ldg(&U[j]));
        d_v[0][j] = vn;
        out[(size_t)0 * OUTW + ofs + j] = vn;
    }
    gsyncC(1u * NBLK, ctr);             // also orders s_cst for the loop

    for (int t = 1; t < TSTEPS; t++) {
        const float* __restrict__ vsrc = d_v[(t - 1) & 1];
        float*       __restrict__ vdst = d_v[t & 1];

        // prefetch U[t] (independent of staging)
        float uval = 0.f;
        if (lane == 0) uval = __ldg(&U[(size_t)t * RN + j0 + wrp]);

        // stage v(t-1) into smem (bypass L1: written by other SMs)
        const float4* vp = reinterpret_cast<const float4*>(vsrc);
        for (int i = tid; i < RN / 4; i += NTHR)
            reinterpret_cast<float4*>(vs)[i] = __ldcg(vp + i);
        __syncthreads();

        // warp w -> column j0+w; publish immediately when done
        {
            const int ps = s_cst[wrp];
            const int pe = s_cst[wrp + 1];
            float acc = 0.f;
#pragma unroll 4
            for (int p = ps + lane; p < pe; p += 32)
                acc += __ldg(&gvals[p]) * vs[__ldg(&grows[p])];
#pragma unroll
            for (int off = 16; off > 0; off >>= 1)
                acc += __shfl_down_sync(0xffffffffu, acc, off);
            if (lane == 0) {
                const int j = j0 + wrp;
                float z  = acc + uval;
                float vn = (1.f - ALPHA) * vs[j] + ALPHA * tanhf(z);
                vdst[j] = vn;                              // hot publish
                out[(size_t)t * OUTW + ofs + j] = vn;      // archive
            }
        }

        if (t < TSTEPS - 1)
            gsyncC((unsigned)(t + 1) * NBLK, ctr);
    }
}

__global__ __launch_bounds__(NTHR, 1) void esn1Kernel(float* __restrict__ out) {
    esn_chain(d_colptr1, d_vals1, d_rows1, d_U1, out, 0, &g_ctr1);
}

__global__ __launch_bounds__(NTHR, 1) void esn2Kernel(float* __restrict__ out) {
    esn_chain(d_colptr2, d_vals2, d_rows2, d_U2, out, RN, &g_ctr2);
}

// ---------------- launch ----------------
extern "C" void kernel_launch(void* const* d_in, const int* in_sizes, int n_in,
                              void* d_out, int out_size) {
    const float* x    = (const float*)d_in[0];
    const float* Win1 = (const float*)d_in[1];
    const float* W1   = (const float*)d_in[2];
    const float* Win2 = (const float*)d_in[3];
    const float* W2   = (const float*)d_in[4];
    float* out = (float*)d_out;
    (void)in_sizes; (void)n_in; (void)out_size;

    // count roles + GEMM1 roles overlapped (independent work, no sync)
    buildGemm1Kernel<<<506, 256>>>(W1, W2, x, Win1);
    scanKernel<<<2, 1024>>>();
    fillKernel<<<250, 256>>>(W1, W2);

    // v1 chain -> out[:, 0:4000]
    esn1Kernel<<<NBLK, NTHR>>>(out);

    // U2 = V1[1000,4000] @ Win2[4000,4000]  (V1 rows in out, stride OUTW)
    dim3 gg((RN + 127) / 128, (TSTEPS + 127) / 128);
    sgemm2K<<<gg, 256>>>(out, Win2, TSTEPS, RN, RN, OUTW, RN, RN);

    // v2 chain -> out[:, 4000:8000]
    esn2Kernel<<<NBLK, NTHR>>>(out);
}

// round 15
// speedup vs baseline: 1.5097x; 1.0077x over previous
#include <cuda_runtime.h>
#include <math.h>

// ---------------- problem constants ----------------
#define TSTEPS 1000
#define NIN    4096
#define RN     4000
#define OUTW   (2*RN)
#define ALPHA  0.5f

// ---------------- persistent loop config (R10-proven) ----------------
#define NBLK   125             // 125 tiles x 32 columns = 4000
#define NTHR   1024

#define NNZ_CAP 1800000

// ---------------- device scratch ----------------
__device__ float          d_vals1[NNZ_CAP];
__device__ unsigned short d_rows1[NNZ_CAP];
__device__ float          d_vals2[NNZ_CAP];
__device__ unsigned short d_rows2[NNZ_CAP];
__device__ int            d_colptr1[RN+1];
__device__ int            d_colptr2[RN+1];
__device__ int            d_cntW1[8*RN];
__device__ int            d_cntW2[8*RN];
__device__ float          d_U1[TSTEPS*RN];    // x @ Win1   (16 MB)
__device__ float          d_U2[TSTEPS*RN];    // V1 @ Win2  (16 MB)
__device__ float          d_v[2][RN];         // hot ping-pong state
__device__ unsigned       g_ctr1;             // monotonic barrier counters
__device__ unsigned       g_ctr2;

// ---------------- packed f32x2 helpers (sm_103a FFMA2 pipe) -----------------
__device__ __forceinline__ unsigned long long dupf2(float v) {
    unsigned long long r;
    asm("mov.b64 %0, {%1, %2};" : "=l"(r) : "f"(v), "f"(v));
    return r;
}
__device__ __forceinline__ void fmaf2(unsigned long long &d,
                                      unsigned long long a,
                                      unsigned long long b) {
    asm("fma.rn.f32x2 %0, %1, %2, %0;" : "+l"(d) : "l"(a), "l"(b));
}
__device__ __forceinline__ float2 unpk(unsigned long long v) {
    float2 r;
    asm("mov.b64 {%0, %1}, %2;" : "=f"(r.x), "=f"(r.y) : "l"(v));
    return r;
}

// ---------------- scoped sync primitives ----------------
__device__ __forceinline__ void redAddRel(unsigned* p) {
    asm volatile("red.release.gpu.global.add.u32 [%0], 1;"
                 :: "l"(p) : "memory");
}
__device__ __forceinline__ unsigned ldAcq(const unsigned* p) {
    unsigned v;
    asm volatile("ld.acquire.gpu.global.u32 %0, [%1];"
                 : "=r"(v) : "l"(p) : "memory");
    return v;
}

// ---------------- count kernel (also resets barrier counters) ---------------
__global__ void countKernel(const float* __restrict__ W1,
                            const float* __restrict__ W2) {
    int b = blockIdx.x;
    if (b == 0 && threadIdx.x == 0) { g_ctr1 = 0u; g_ctr2 = 0u; }
    const float* W; int* cntW; int j0;
    if (b < 125) { W = W1; cntW = d_cntW1; j0 = b * 32; }
    else         { W = W2; cntW = d_cntW2; j0 = (b - 125) * 32; }
    int w = threadIdx.x >> 5, lane = threadIdx.x & 31;
    int j = j0 + lane;
    int c = 0;
    int i0 = w * 500, i1 = i0 + 500;
    for (int i = i0; i < i1; i++) c += (W[(size_t)i * RN + j] != 0.f);
    cntW[w * RN + j] = c;
}

// ---------------- exclusive scan ----------------
__global__ void scanKernel() {
    __shared__ int sA[4096], sB[4096];
    const int* cntW = (blockIdx.x == 0) ? d_cntW1 : d_cntW2;
    int* colptr     = (blockIdx.x == 0) ? d_colptr1 : d_colptr2;
    int tid = threadIdx.x;
    for (int i = tid; i < 4096; i += blockDim.x) {
        int tot = 0;
        if (i < RN)
            for (int w = 0; w < 8; w++) tot += cntW[w * RN + i];
        sA[i] = tot;
    }
    __syncthreads();
    int* src = sA; int* dst = sB;
    for (int off = 1; off < 4096; off <<= 1) {
        for (int i = tid; i < 4096; i += blockDim.x)
            dst[i] = src[i] + (i >= off ? src[i - off] : 0);
        __syncthreads();
        int* t = src; src = dst; dst = t;
    }
    for (int i = tid; i < RN; i += blockDim.x) colptr[i + 1] = src[i];
    if (tid == 0) colptr[0] = 0;
}

// ---------------- GEMM1 tile body: d_U1[128x128 tile] = x @ Win1 ------------
__device__ void gemm1_tile(const float* __restrict__ A,
                           const float* __restrict__ B,
                           int row0, int col0) {
    const int M = TSTEPS, N = RN, K = NIN, lda = NIN, ldb = RN, ldc = RN;
    float* __restrict__ C = d_U1;
    __shared__ float As[8][128];
    __shared__ float Bs[8][128];
    int tid = threadIdx.x;
    int tx = tid % 16, ty = tid / 16;

    unsigned long long acc2[4][8];
#pragma unroll
    for (int p = 0; p < 4; p++)
#pragma unroll
        for (int j = 0; j < 8; j++) acc2[p][j] = 0ull;

    const int aRow = tid >> 1;
    const int aCol = (tid & 1) * 4;
    const int bRow = tid >> 5;
    const int bCol = (tid & 31) * 4;

    float4 a4 = make_float4(0.f, 0.f, 0.f, 0.f);
    if (row0 + aRow < M)
        a4 = *(const float4*)(A + (size_t)(row0 + aRow) * lda + aCol);
    float4 b4 = make_float4(0.f, 0.f, 0.f, 0.f);
    if (col0 + bCol < N)
        b4 = *(const float4*)(B + (size_t)bRow * ldb + col0 + bCol);

    for (int k0 = 0; k0 < K; k0 += 8) {
        As[aCol + 0][aRow] = a4.x; As[aCol + 1][aRow] = a4.y;
        As[aCol + 2][aRow] = a4.z; As[aCol + 3][aRow] = a4.w;
        *(float4*)(&Bs[bRow][bCol]) = b4;
        __syncthreads();

        if (k0 + 8 < K) {
            if (row0 + aRow < M)
                a4 = *(const float4*)(A + (size_t)(row0 + aRow) * lda + k0 + 8 + aCol);
            if (col0 + bCol < N)
                b4 = *(const float4*)(B + (size_t)(k0 + 8 + bRow) * ldb + col0 + bCol);
        }

#pragma unroll
        for (int kk = 0; kk < 8; kk++) {
            float4 a0 = *(const float4*)(&As[kk][ty * 4]);
            float4 a1 = *(const float4*)(&As[kk][64 + ty * 4]);
            float4 bb0 = *(const float4*)(&Bs[kk][tx * 4]);
            float4 bb1 = *(const float4*)(&Bs[kk][64 + tx * 4]);
            unsigned long long ap[4];
            ap[0] = reinterpret_cast<const ulonglong2*>(&a0)->x;
            ap[1] = reinterpret_cast<const ulonglong2*>(&a0)->y;
            ap[2] = reinterpret_cast<const ulonglong2*>(&a1)->x;
            ap[3] = reinterpret_cast<const ulonglong2*>(&a1)->y;
            unsigned long long bd[8];
            bd[0] = dupf2(bb0.x); bd[1] = dupf2(bb0.y);
            bd[2] = dupf2(bb0.z); bd[3] = dupf2(bb0.w);
            bd[4] = dupf2(bb1.x); bd[5] = dupf2(bb1.y);
            bd[6] = dupf2(bb1.z); bd[7] = dupf2(bb1.w);
#pragma unroll
            for (int p = 0; p < 4; p++)
#pragma unroll
                for (int j = 0; j < 8; j++)
                    fmaf2(acc2[p][j], ap[p], bd[j]);
        }
        __syncthreads();
    }

#pragma unroll
    for (int p = 0; p < 4; p++) {
        float2 u[8];
#pragma unroll
        for (int j = 0; j < 8; j++) u[j] = unpk(acc2[p][j]);
#pragma unroll
        for (int h = 0; h < 2; h++) {
            int i = 2 * p + h;
            int r = row0 + ((i < 4) ? (ty * 4 + i) : (64 + ty * 4 + i - 4));
            if (r >= M) continue;
            float4 v0 = make_float4(h ? u[0].y : u[0].x, h ? u[1].y : u[1].x,
                                    h ? u[2].y : u[2].x, h ? u[3].y : u[3].x);
            float4 v1 = make_float4(h ? u[4].y : u[4].x, h ? u[5].y : u[5].x,
                                    h ? u[6].y : u[6].x, h ? u[7].y : u[7].x);
            int c0 = col0 + tx * 4;
            int c1 = col0 + 64 + tx * 4;
            if (c0 < N) *(float4*)(C + (size_t)r * ldc + c0) = v0;
            if (c1 < N) *(float4*)(C + (size_t)r * ldc + c1) = v1;
        }
    }
}

// ---------------- fused kernel: fill roles + GEMM1 roles --------------------
// Blocks 0..249: CSC fill (needs scan done -> launched after scanKernel).
// Blocks 250..505: GEMM1 tiles. Disjoint data, no synchronization.
__global__ __launch_bounds__(256, 2) void fillGemm1Kernel(
        const float* __restrict__ W1, const float* __restrict__ W2,
        const float* __restrict__ x,  const float* __restrict__ Win1) {
    int b = blockIdx.x;
    if (b < 250) {
        const float* W; const int* cntW; const int* colptr;
        float* vals; unsigned short* rows; int j0;
        if (b < 125) { W = W1; cntW = d_cntW1; colptr = d_colptr1;
                       vals = d_vals1; rows = d_rows1; j0 = b * 32; }
        else         { W = W2; cntW = d_cntW2; colptr = d_colptr2;
                       vals = d_vals2; rows = d_rows2; j0 = (b - 125) * 32; }
        int w = threadIdx.x >> 5, lane = threadIdx.x & 31;
        int j = j0 + lane;
        int p = colptr[j];
        for (int w2 = 0; w2 < 8; w2++)
            if (w2 < w) p += cntW[w2 * RN + j];
        int i0 = w * 500, i1 = i0 + 500;
        for (int i = i0; i < i1; i++) {
            float v = W[(size_t)i * RN + j];
            if (v != 0.f) { vals[p] = v; rows[p] = (unsigned short)i; p++; }
        }
    } else {
        int p = b - 250;                   // 0..255
        gemm1_tile(x, Win1, (p >> 5) * 128, (p & 31) * 128);
    }
}

// ---------------- SGEMM2 (separate launch): d_U2 = V1 @ Win2 ----------------
// C resolved device-side (device globals must never be host-side kernel args).
__global__ __launch_bounds__(256, 2) void sgemm2K(const float* __restrict__ A,
                                                  const float* __restrict__ B,
                                                  int M, int N, int K,
                                                  int lda, int ldb, int ldc) {
    float* __restrict__ C = d_U2;
    __shared__ float As[8][128];
    __shared__ float Bs[8][128];
    int tid = threadIdx.x;
    int tx = tid % 16, ty = tid / 16;
    int row0 = blockIdx.y * 128, col0 = blockIdx.x * 128;

    unsigned long long acc2[4][8];
#pragma unroll
    for (int p = 0; p < 4; p++)
#pragma unroll
        for (int j = 0; j < 8; j++) acc2[p][j] = 0ull;

    const int aRow = tid >> 1;
    const int aCol = (tid & 1) * 4;
    const int bRow = tid >> 5;
    const int bCol = (tid & 31) * 4;

    float4 a4 = make_float4(0.f, 0.f, 0.f, 0.f);
    if (row0 + aRow < M)
        a4 = *(const float4*)(A + (size_t)(row0 + aRow) * lda + aCol);
    float4 b4 = make_float4(0.f, 0.f, 0.f, 0.f);
    if (col0 + bCol < N)
        b4 = *(const float4*)(B + (size_t)bRow * ldb + col0 + bCol);

    for (int k0 = 0; k0 < K; k0 += 8) {
        As[aCol + 0][aRow] = a4.x; As[aCol + 1][aRow] = a4.y;
        As[aCol + 2][aRow] = a4.z; As[aCol + 3][aRow] = a4.w;
        *(float4*)(&Bs[bRow][bCol]) = b4;
        __syncthreads();

        if (k0 + 8 < K) {
            if (row0 + aRow < M)
                a4 = *(const float4*)(A + (size_t)(row0 + aRow) * lda + k0 + 8 + aCol);
            if (col0 + bCol < N)
                b4 = *(const float4*)(B + (size_t)(k0 + 8 + bRow) * ldb + col0 + bCol);
        }

#pragma unroll
        for (int kk = 0; kk < 8; kk++) {
            float4 a0 = *(const float4*)(&As[kk][ty * 4]);
            float4 a1 = *(const float4*)(&As[kk][64 + ty * 4]);
            float4 bb0 = *(const float4*)(&Bs[kk][tx * 4]);
            float4 bb1 = *(const float4*)(&Bs[kk][64 + tx * 4]);
            unsigned long long ap[4];
            ap[0] = reinterpret_cast<const ulonglong2*>(&a0)->x;
            ap[1] = reinterpret_cast<const ulonglong2*>(&a0)->y;
            ap[2] = reinterpret_cast<const ulonglong2*>(&a1)->x;
            ap[3] = reinterpret_cast<const ulonglong2*>(&a1)->y;
            unsigned long long bd[8];
            bd[0] = dupf2(bb0.x); bd[1] = dupf2(bb0.y);
            bd[2] = dupf2(bb0.z); bd[3] = dupf2(bb0.w);
            bd[4] = dupf2(bb1.x); bd[5] = dupf2(bb1.y);
            bd[6] = dupf2(bb1.z); bd[7] = dupf2(bb1.w);
#pragma unroll
            for (int p = 0; p < 4; p++)
#pragma unroll
                for (int j = 0; j < 8; j++)
                    fmaf2(acc2[p][j], ap[p], bd[j]);
        }
        __syncthreads();
    }

#pragma unroll
    for (int p = 0; p < 4; p++) {
        float2 u[8];
#pragma unroll
        for (int j = 0; j < 8; j++) u[j] = unpk(acc2[p][j]);
#pragma unroll
        for (int h = 0; h < 2; h++) {
            int i = 2 * p + h;
            int r = row0 + ((i < 4) ? (ty * 4 + i) : (64 + ty * 4 + i - 4));
            if (r >= M) continue;
            float4 v0 = make_float4(h ? u[0].y : u[0].x, h ? u[1].y : u[1].x,
                                    h ? u[2].y : u[2].x, h ? u[3].y : u[3].x);
            float4 v1 = make_float4(h ? u[4].y : u[4].x, h ? u[5].y : u[5].x,
                                    h ? u[6].y : u[6].x, h ? u[7].y : u[7].x);
            int c0 = col0 + tx * 4;
            int c1 = col0 + 64 + tx * 4;
            if (c0 < N) *(float4*)(C + (size_t)r * ldc + c0) = v0;
            if (c1 < N) *(float4*)(C + (size_t)r * ldc + c1) = v1;
        }
    }
}

// ---------------- grid barrier: RED arrival + counter poll (R10-proven) -----
__device__ __forceinline__ void gsyncC(unsigned target, unsigned* ctr) {
    __syncthreads();
    if (threadIdx.x == 0) {
        redAddRel(ctr);                  // fire-and-forget arrival
        while (ldAcq(ctr) < target) { }  // counter reaching target = release
    }
    __syncthreads();
}

// ---------------- sparse-only recurrence (R14-proven + archive post-barrier) -
// Block b owns columns [b*32, b*32+32). CSC slice is L1-resident after step 1.
// v(t) = 0.5*v(t-1) + 0.5*tanh( v(t-1)@W + U[t] ),  v(-1)=0
// The hot d_v publish stays BEFORE the barrier (release set); the `out`
// archive store moves AFTER arrival — it is only read by LATER kernel
// launches (kernel boundary is a full fence), so it need not burden the
// per-step release ordering.
__device__ __forceinline__ void esn_chain(const int* __restrict__ colptr,
                                          const float* __restrict__ gvals,
                                          const unsigned short* __restrict__ grows,
                                          const float* __restrict__ U,
                                          float* __restrict__ out, int ofs,
                                          unsigned* ctr) {
    __shared__ float vs[RN];
    __shared__ int s_cst[33];

    const int tid  = threadIdx.x;
    const int lane = tid & 31;
    const int wrp  = tid >> 5;          // 0..31 -> one column each
    const int j0   = blockIdx.x * 32;
    const int jcol = j0 + wrp;

    if (tid < 33) s_cst[tid] = __ldg(&colptr[j0 + tid]);

    // t = 0 : v(0) = 0.5*tanh(U[0])
    float vn_keep = 0.f;
    if (lane == 0) {
        vn_keep = ALPHA * tanhf(__ldg(&U[jcol]));
        d_v[0][jcol] = vn_keep;
    }
    gsyncC(1u * NBLK, ctr);             // also orders s_cst for the loop
    if (lane == 0) out[(size_t)0 * OUTW + ofs + jcol] = vn_keep;  // archive

    for (int t = 1; t < TSTEPS; t++) {
        const float* __restrict__ vsrc = d_v[(t - 1) & 1];
        float*       __restrict__ vdst = d_v[t & 1];

        // prefetch U[t] (independent of staging)
        float uval = 0.f;
        if (lane == 0) uval = __ldg(&U[(size_t)t * RN + jcol]);

        // stage v(t-1) into smem (bypass L1: written by other SMs)
        const float4* vp = reinterpret_cast<const float4*>(vsrc);
        for (int i = tid; i < RN / 4; i += NTHR)
            reinterpret_cast<float4*>(vs)[i] = __ldcg(vp + i);
        __syncthreads();

        // warp w -> column j0+w; hot publish before barrier
        {
            const int ps = s_cst[wrp];
            const int pe = s_cst[wrp + 1];
            float acc = 0.f;
#pragma unroll 4
            for (int p = ps + lane; p < pe; p += 32)
                acc += __ldg(&gvals[p]) * vs[__ldg(&grows[p])];
#pragma unroll
            for (int off = 16; off > 0; off >>= 1)
                acc += __shfl_down_sync(0xffffffffu, acc, off);
            if (lane == 0) {
                float z = acc + uval;
                vn_keep = (1.f - ALPHA) * vs[jcol] + ALPHA * tanhf(z);
                vdst[jcol] = vn_keep;                      // hot publish
            }
        }

        if (t < TSTEPS - 1)
            gsyncC((unsigned)(t + 1) * NBLK, ctr);

        // archive AFTER arrival: off the release-ordering path
        if (lane == 0) out[(size_t)t * OUTW + ofs + jcol] = vn_keep;
    }
}

__global__ __launch_bounds__(NTHR, 1) void esn1Kernel(float* __restrict__ out) {
    esn_chain(d_colptr1, d_vals1, d_rows1, d_U1, out, 0, &g_ctr1);
}

__global__ __launch_bounds__(NTHR, 1) void esn2Kernel(float* __restrict__ out) {
    esn_chain(d_colptr2, d_vals2, d_rows2, d_U2, out, RN, &g_ctr2);
}

// ---------------- launch ----------------
extern "C" void kernel_launch(void* const* d_in, const int* in_sizes, int n_in,
                              void* d_out, int out_size) {
    const float* x    = (const float*)d_in[0];
    const float* Win1 = (const float*)d_in[1];
    const float* W1   = (const float*)d_in[2];
    const float* Win2 = (const float*)d_in[3];
    const float* W2   = (const float*)d_in[4];
    float* out = (float*)d_out;
    (void)in_sizes; (void)n_in; (void)out_size;

    countKernel<<<250, 256>>>(W1, W2);          // + barrier-counter reset
    scanKernel<<<2, 1024>>>();
    fillGemm1Kernel<<<506, 256>>>(W1, W2, x, Win1);   // fill || GEMM1

    // v1 chain -> out[:, 0:4000]
    esn1Kernel<<<NBLK, NTHR>>>(out);

    // U2 = V1[1000,4000] @ Win2[4000,4000]  (V1 rows in out, stride OUTW)
    dim3 gg((RN + 127) / 128, (TSTEPS + 127) / 128);
    sgemm2K<<<gg, 256>>>(out, Win2, TSTEPS, RN, RN, OUTW, RN, RN);

    // v2 chain -> out[:, 4000:8000]
    esn2Kernel<<<NBLK, NTHR>>>(out);
}